// round 12
// baseline (speedup 1.0000x reference)
#include <cuda_runtime.h>
#include <cuda_bf16.h>
#include <math_constants.h>
#include <cstdint>

#define DD 128
#define BQ 32
#define KTOP 16
#define TILE_R 128
#define TPB 256
#define NCTA 148
#define SCST 34

// smem byte offsets
#define SM_F0   0              // fp32 tile buf 0 (64 KB)
#define SM_F1   65536          // fp32 tile buf 1 (64 KB)
#define SM_AHI  131072         // 128 rows x 256B bf16
#define SM_QHI  163840         // 32 rows x 256B bf16
#define SM_SC   172032         // 128*34*4 = 17408
#define SM_MN   189440         // 256 floats
#define SM_RW   190464         // 128 floats
#define SM_W    190976         // 128 floats
#define SM_CB   191488         // 32 floats
#define SM_TH   191616         // 32 floats
#define SM_FLG  191744         // 32 ints
#define SM_MBAR 191872         // 2 x 8B mbarriers
#define SMEM_BYTES 191904

__device__ float g_q[BQ*DD];
__device__ float g_qn[BQ];
__device__ float g_cand_s[NCTA*BQ*KTOP];
__device__ int   g_cand_i[NCTA*BQ*KTOP];
__device__ float g_minred[NCTA*BQ];

// ---------------- helpers ----------------
__device__ __forceinline__ uint32_t smem_u32(const void* p) {
    uint32_t a;
    asm("{ .reg .u64 t; cvta.to.shared.u64 t, %1; cvt.u32.u64 %0, t; }" : "=r"(a) : "l"(p));
    return a;
}
__device__ __forceinline__ void tma_bulk_g2s(uint32_t dst, const void* src, uint32_t bytes, uint32_t mbar) {
    asm volatile("cp.async.bulk.shared::cluster.global.mbarrier::complete_tx::bytes [%0], [%1], %2, [%3];"
                 :: "r"(dst), "l"(src), "r"(bytes), "r"(mbar) : "memory");
}
#define MBARRIER_INIT(mb, cnt) \
    asm volatile("mbarrier.init.shared.b64 [%0], %1;" :: "r"((uint32_t)(mb)), "r"((uint32_t)(cnt)) : "memory")
#define MBARRIER_EXPECT_TX(mb, tx) \
    asm volatile("mbarrier.arrive.expect_tx.shared.b64 _, [%0], %1;" :: "r"((uint32_t)(mb)), "r"((uint32_t)(tx)) : "memory")
#define MBARRIER_WAIT_PARITY(mb, ph) do { \
    uint32_t _m = (uint32_t)(mb), _p = (uint32_t)(ph), _d; \
    asm volatile("{ .reg .pred p; mbarrier.try_wait.parity.acquire.cta.shared::cta.b64 p, [%1], %2; selp.b32 %0, 1, 0, p; }" \
                 : "=r"(_d) : "r"(_m), "r"(_p) : "memory"); \
    if (!_d) { \
        asm volatile("{ .reg .pred P1; WL_%=: mbarrier.try_wait.parity.acquire.cta.shared::cta.b64 P1, [%0], %1, 0x989680; @P1 bra.uni WD_%=; bra.uni WL_%=; WD_%=: }" \
                     :: "r"(_m), "r"(_p) : "memory"); \
    } \
} while (0)

__device__ __forceinline__ void fma2(unsigned long long& d, unsigned long long a, unsigned long long b) {
    asm("fma.rn.f32x2 %0, %1, %2, %0;" : "+l"(d) : "l"(a), "l"(b));
}
__device__ __forceinline__ void unpack2(unsigned long long v, float& lo, float& hi) {
    asm("mov.b64 {%0, %1}, %2;" : "=f"(lo), "=f"(hi) : "l"(v));
}
__device__ __forceinline__ uint32_t pack_bf16x2(float hi_elem, float lo_elem) {
    uint32_t r;
    asm("cvt.rn.bf16x2.f32 %0, %1, %2;" : "=r"(r) : "f"(hi_elem), "f"(lo_elem));
    return r;
}
__device__ __forceinline__ float rsqrt_nr(float x) {
    float r;
    asm("rsqrt.approx.f32 %0, %1;" : "=f"(r) : "f"(x));
    r = r * fmaf(-0.5f * x * r, r, 1.5f);
    return r;
}
__device__ __forceinline__ void ldsm_x4(uint32_t& r0, uint32_t& r1, uint32_t& r2, uint32_t& r3, uint32_t a) {
    asm volatile("ldmatrix.sync.aligned.m8n8.x4.shared.b16 {%0,%1,%2,%3}, [%4];"
                 : "=r"(r0), "=r"(r1), "=r"(r2), "=r"(r3) : "r"(a));
}
__device__ __forceinline__ void ldsm_x2(uint32_t& r0, uint32_t& r1, uint32_t a) {
    asm volatile("ldmatrix.sync.aligned.m8n8.x2.shared.b16 {%0,%1}, [%2];"
                 : "=r"(r0), "=r"(r1) : "r"(a));
}
__device__ __forceinline__ void mma16816(float* c, uint32_t a0, uint32_t a1, uint32_t a2, uint32_t a3,
                                         uint32_t b0, uint32_t b1) {
    asm volatile("mma.sync.aligned.m16n8k16.row.col.f32.bf16.bf16.f32 "
                 "{%0,%1,%2,%3}, {%4,%5,%6,%7}, {%8,%9}, {%0,%1,%2,%3};"
                 : "+f"(c[0]), "+f"(c[1]), "+f"(c[2]), "+f"(c[3])
                 : "r"(a0), "r"(a1), "r"(a2), "r"(a3), "r"(b0), "r"(b1));
}

// ---------------------------------------------------------------------------
// k_main: setup + TMA-staged bf16 HMMA dots + reject-filtered top-16 + min-d2
// ---------------------------------------------------------------------------
__global__ void __launch_bounds__(TPB, 1)
k_main(const float* __restrict__ query, const float* __restrict__ mem,
       const float* __restrict__ imp, const int* __restrict__ ts,
       const float* __restrict__ Wq, const float* __restrict__ bqv,
       const int* __restrict__ ctp, int N, int tpc) {
    extern __shared__ char smem[];
    const uint32_t sb = smem_u32(smem);
    float* sSC  = (float*)(smem + SM_SC);
    float* sMN  = (float*)(smem + SM_MN);
    float* sRW  = (float*)(smem + SM_RW);
    float* sW   = (float*)(smem + SM_W);
    float* sCB  = (float*)(smem + SM_CB);
    float* sTH  = (float*)(smem + SM_TH);
    int*   sFLG = (int*)(smem + SM_FLG);

    const int t    = threadIdx.x;
    const int wid  = t >> 5;
    const int lane = t & 31;
    const int cta  = blockIdx.x;

    // ===== setup: exact q = query @ Wq^T + bq; Qhi bf16 operand =====
    {
        float* sQT = (float*)(smem + SM_F0);
        float* sQF = (float*)(smem + SM_F1);
        for (int o = t; o < BQ*DD; o += TPB) sQT[o] = query[o];
        __syncthreads();
        for (int o = t; o < BQ*DD; o += TPB) {
            int b = o >> 7, j = o & 127;
            const float4* wr = (const float4*)(Wq + (size_t)j * DD);
            const float4* qr = (const float4*)(sQT + b * DD);
            float a0 = 0.f, a1 = 0.f, a2 = 0.f, a3 = 0.f;
            #pragma unroll 8
            for (int dd = 0; dd < 32; dd++) {
                float4 wv = wr[dd]; float4 qv = qr[dd];
                a0 = fmaf(qv.x, wv.x, a0); a1 = fmaf(qv.y, wv.y, a1);
                a2 = fmaf(qv.z, wv.z, a2); a3 = fmaf(qv.w, wv.w, a3);
            }
            float v = ((a0 + a1) + (a2 + a3)) + bqv[j];
            sQF[o] = v;
            g_q[o] = v;
        }
        __syncthreads();
        if (t < BQ) {
            float s = 0.f;
            for (int jj = 0; jj < DD; jj++) {
                int j = (jj + 5*t) & 127;
                float v = sQF[t*DD + j];
                s = fmaf(v, v, s);
            }
            float qn = sqrtf(s);
            g_qn[t] = qn;
            sCB[t] = 0.7f / qn;
            sTH[t] = -CUDART_INF_F;
            sFLG[t] = 0;
        }
        for (int o = t; o < BQ*DD; o += TPB) {
            int b = o >> 7, j = o & 127;
            *(__nv_bfloat16*)(smem + SM_QHI + b*256 + (((j >> 3) ^ (b & 7)) << 4) + (j & 7)*2)
                = __float2bfloat16(sQF[o]);
        }
        __syncthreads();
    }

    // ===== mbarriers =====
    if (t == 0) {
        MBARRIER_INIT(sb + SM_MBAR,     1);
        MBARRIER_INIT(sb + SM_MBAR + 8, 1);
    }
    __syncthreads();

    const float inv_ct1 = 1.0f / ((float)(*ctp) + 1.0f);

    float lmn[8];
    #pragma unroll
    for (int j = 0; j < 8; j++) lmn[j] = CUDART_INF_F;
    float hv[KTOP]; int hx[KTOP];
    #pragma unroll
    for (int j = 0; j < KTOP; j++) { hv[j] = -CUDART_INF_F; hx[j] = 0x7fffffff; }

    const long tile0 = (long)cta * tpc;

    const int cr = t & 127;
    const int ch = t >> 7;
    const int slab = wid * 16;
    const int rA   = slab + (lane & 15);
    const uint32_t aBase = sb + SM_AHI + rA * 256;
    const int aSel = lane >> 4;
    const int qB   = lane & 7;
    const int bSel = (lane >> 3) & 1;
    const int gid  = lane >> 2;
    const int tig  = lane & 3;

    int ph0 = 0, ph1 = 0;

    // prologue: stage tile 0 into F0
    {
        int base = (int)(tile0 * TILE_R);
        if (base < N) {
            if (base + TILE_R <= N) {
                if (t == 0) {
                    MBARRIER_EXPECT_TX(sb + SM_MBAR, 65536u);
                    tma_bulk_g2s(sb + SM_F0, mem + (size_t)base * DD, 65536u, sb + SM_MBAR);
                }
            } else {
                float4* raw = (float4*)(smem + SM_F0);
                const float4* gsrc = (const float4*)(mem + (size_t)base * DD);
                for (int j = 0; j < 16; j++) {
                    int fi = t + TPB*j, row = fi >> 5;
                    float4 v = make_float4(0.f, 0.f, 0.f, 0.f);
                    if (base + row < N) v = gsrc[fi];
                    raw[fi] = v;
                }
            }
        }
    }
    __syncthreads();

    for (int it = 0; it < tpc; it++) {
        int base = (int)((tile0 + it) * TILE_R);
        if (base >= N) break;
        const bool fulli = (base + TILE_R <= N);
        const int curF = (it & 1) ? SM_F1 : SM_F0;

        // wait for this tile's TMA (partial tiles were staged manually)
        if (fulli) {
            if ((it & 1) == 0) { MBARRIER_WAIT_PARITY(sb + SM_MBAR,     ph0); ph0 ^= 1; }
            else               { MBARRIER_WAIT_PARITY(sb + SM_MBAR + 8, ph1); ph1 ^= 1; }
        }

        // stage next tile (TMA for full, manual for partial)
        {
            int nbase = (int)((tile0 + it + 1) * TILE_R);
            if (it + 1 < tpc && nbase < N) {
                const int nF = ((it + 1) & 1) ? SM_F1 : SM_F0;
                const uint32_t nmb = sb + SM_MBAR + (((it + 1) & 1) ? 8 : 0);
                if (nbase + TILE_R <= N) {
                    if (t == 0) {
                        MBARRIER_EXPECT_TX(nmb, 65536u);
                        tma_bulk_g2s(sb + nF, mem + (size_t)nbase * DD, 65536u, nmb);
                    }
                } else {
                    float4* raw = (float4*)(smem + nF);
                    const float4* gsrc = (const float4*)(mem + (size_t)nbase * DD);
                    for (int j = 0; j < 16; j++) {
                        int fi = t + TPB*j, row = fi >> 5;
                        float4 v = make_float4(0.f, 0.f, 0.f, 0.f);
                        if (nbase + row < N) v = gsrc[fi];
                        raw[fi] = v;
                    }
                }
            }
        }

        // per-row scalars
        if (t < TILE_R) {
            int row = base + t;
            if (row < N) {
                sRW[t] = 0.3f * ((float)ts[row] + 1.0f) * inv_ct1;
                sW[t]  = fmaf(0.5f, imp[row], 0.5f);
            }
        }

        // convert fp32 (linear) -> Ahi bf16 (ldmatrix swizzle) + half norms
        {
            const float* ra = (const float*)(smem + curF) + cr*DD;
            unsigned long long nacc = 0ULL;
            #pragma unroll 4
            for (int cc = 0; cc < 16; cc++) {
                int lc = (2*cc + ch) ^ (cr & 7);           // logical == physical chunk
                float4 v = *(const float4*)(ra + (lc << 2));
                ulonglong2 u = *reinterpret_cast<ulonglong2*>(&v);
                fma2(nacc, u.x, u.x);
                fma2(nacc, u.y, u.y);
                uint2 w2;
                w2.x = pack_bf16x2(v.y, v.x);
                w2.y = pack_bf16x2(v.w, v.z);
                int c16 = lc >> 1, half = lc & 1;
                *(uint2*)(smem + SM_AHI + cr*256 + ((c16 ^ (cr & 7)) << 4) + half*8) = w2;
            }
            float nlo, nhi; unpack2(nacc, nlo, nhi);
            sMN[ch*128 + cr] = nlo + nhi;
        }
        __syncthreads();

        // ---- HMMA: 16-row slab x 32 queries, K=128 ----
        float C[4][4];
        #pragma unroll
        for (int nt = 0; nt < 4; nt++)
            #pragma unroll
            for (int i = 0; i < 4; i++) C[nt][i] = 0.f;

        const uint32_t qb0 = sb + SM_QHI + (0*8 + qB)*256;
        const uint32_t qb1 = sb + SM_QHI + (1*8 + qB)*256;
        const uint32_t qb2 = sb + SM_QHI + (2*8 + qB)*256;
        const uint32_t qb3 = sb + SM_QHI + (3*8 + qB)*256;
        #pragma unroll
        for (int ks = 0; ks < 8; ks++) {
            uint32_t a0, a1, a2, a3;
            ldsm_x4(a0, a1, a2, a3, aBase + (((2*ks + aSel) ^ (rA & 7)) << 4));
            uint32_t swz = ((2*ks + bSel) ^ qB) << 4;
            uint32_t b0, b1;
            ldsm_x2(b0, b1, qb0 + swz); mma16816(C[0], a0, a1, a2, a3, b0, b1);
            ldsm_x2(b0, b1, qb1 + swz); mma16816(C[1], a0, a1, a2, a3, b0, b1);
            ldsm_x2(b0, b1, qb2 + swz); mma16816(C[2], a0, a1, a2, a3, b0, b1);
            ldsm_x2(b0, b1, qb3 + swz); mma16816(C[3], a0, a1, a2, a3, b0, b1);
        }

        // ---- epilogue: scores + min-d2 ----
        {
            int rla = slab + gid, rlb = rla + 8;
            bool va = (base + rla < N), vb = (base + rlb < N);
            float mnA = sMN[rla] + sMN[128 + rla];
            float mnB = sMN[rlb] + sMN[128 + rlb];
            float invA = va ? rsqrt_nr(mnA) : 0.f;
            float invB = vb ? rsqrt_nr(mnB) : 0.f;
            float recA = va ? sRW[rla] : 0.f, wA = va ? sW[rla] : 0.f;
            float recB = vb ? sRW[rlb] : 0.f, wB = vb ? sW[rlb] : 0.f;
            #pragma unroll
            for (int nt = 0; nt < 4; nt++) {
                int q0 = nt*8 + tig*2;
                float cb0 = sCB[q0], cb1 = sCB[q0+1];
                float dA0 = C[nt][0], dA1 = C[nt][1];
                float dB0 = C[nt][2], dB1 = C[nt][3];
                float2 sa, sbv;
                sa.x  = va ? fmaf(dA0*invA, cb0, recA) * wA : -CUDART_INF_F;
                sa.y  = va ? fmaf(dA1*invA, cb1, recA) * wA : -CUDART_INF_F;
                sbv.x = vb ? fmaf(dB0*invB, cb0, recB) * wB : -CUDART_INF_F;
                sbv.y = vb ? fmaf(dB1*invB, cb1, recB) * wB : -CUDART_INF_F;
                *(float2*)(sSC + rla*SCST + q0) = sa;
                *(float2*)(sSC + rlb*SCST + q0) = sbv;
                float m0 = CUDART_INF_F, m1 = CUDART_INF_F;
                if (va) { m0 = fmaf(-2.f, dA0, mnA); m1 = fmaf(-2.f, dA1, mnA); }
                if (vb) { m0 = fminf(m0, fmaf(-2.f, dB0, mnB)); m1 = fminf(m1, fmaf(-2.f, dB1, mnB)); }
                lmn[nt*2]   = fminf(lmn[nt*2],   m0);
                lmn[nt*2+1] = fminf(lmn[nt*2+1], m1);
            }
        }
        __syncthreads();

        // ---- phase A: parallel reject test (all 256 threads) ----
        {
            int q = t & 31, chk = t >> 5;
            const float* col = sSC + (chk*16)*SCST + q;
            float mx = -CUDART_INF_F;
            #pragma unroll
            for (int j = 0; j < 16; j++) mx = fmaxf(mx, col[j*SCST]);
            if (mx > sTH[q]) sFLG[q] = 1;
        }
        __syncthreads();

        // ---- phase B: full scan only when flagged (rare) ----
        if (t < BQ && sFLG[t]) {
            sFLG[t] = 0;
            float th = sTH[t];
            for (int e = 0; e < TILE_R; e += 4) {
                float v0 = sSC[(e+0)*SCST + t];
                float v1 = sSC[(e+1)*SCST + t];
                float v2 = sSC[(e+2)*SCST + t];
                float v3 = sSC[(e+3)*SCST + t];
                float mx = fmaxf(fmaxf(v0, v1), fmaxf(v2, v3));
                if (mx > th) {
                    #pragma unroll
                    for (int u = 0; u < 4; u++) {
                        float sc = (u==0)?v0:(u==1)?v1:(u==2)?v2:v3;
                        if (sc > th) {
                            int idx = base + e + u;
                            int pos = KTOP - 1;
                            #pragma unroll
                            for (int s = KTOP - 1; s > 0; s--)
                                if (sc > hv[s-1]) { hv[s] = hv[s-1]; hx[s] = hx[s-1]; pos = s-1; }
                            hv[pos] = sc; hx[pos] = idx;
                            th = hv[KTOP-1];
                        }
                    }
                }
            }
            sTH[t] = th;
        }
        // (no barrier: next iteration's convert-sync orders phase B before sSC reuse)
    }
    __syncthreads();

    // ---- reduce lmn: thread covers q = nt*8 + tig*2 + p ----
    #pragma unroll
    for (int nt = 0; nt < 4; nt++)
        #pragma unroll
        for (int p = 0; p < 2; p++) {
            int q = nt*8 + tig*2 + p;
            sSC[q*64 + wid*8 + gid] = lmn[nt*2+p];
        }
    __syncthreads();
    if (t < BQ) {
        float m = CUDART_INF_F;
        for (int i = 0; i < 64; i++) m = fminf(m, sSC[t*64 + ((i + t) & 63)]);
        g_minred[cta*BQ + t] = m;
        float* cs = g_cand_s + ((size_t)cta*BQ + t) * KTOP;
        int*   ci = g_cand_i + ((size_t)cta*BQ + t) * KTOP;
        #pragma unroll
        for (int j = 0; j < KTOP; j++) { cs[j] = hv[j]; ci[j] = hx[j]; }
    }
}

// ---------------------------------------------------------------------------
// k_topk: approx top-32 merge, exact fp32 rescoring, emit exact top-16
// ---------------------------------------------------------------------------
#define MCAND (NCTA*KTOP)
__global__ void __launch_bounds__(256)
k_topk(const float* __restrict__ mem, const float* __restrict__ imp,
       const int* __restrict__ ts, const int* __restrict__ ctp,
       float* __restrict__ out) {
    __shared__ float cs[MCAND];
    __shared__ int   ci[MCAND];
    __shared__ float rv[256];
    __shared__ int   ri[256], rp[256];
    __shared__ int   candI[32];
    __shared__ float exS[32];
    __shared__ int   exI[32];

    int q = blockIdx.x;
    int t = threadIdx.x;

    for (int i = t; i < MCAND; i += 256) {
        int c = i >> 4, j = i & (KTOP-1);
        size_t g = ((size_t)c*BQ + q) * KTOP + j;
        cs[i] = g_cand_s[g];
        ci[i] = g_cand_i[g];
    }
    __syncthreads();

    for (int pass = 0; pass < 32; pass++) {
        float bv = -CUDART_INF_F; int bi = 0x7fffffff, bp = 0;
        for (int i = t; i < MCAND; i += 256) {
            float v = cs[i]; int id = ci[i];
            if (v > bv || (v == bv && id < bi)) { bv = v; bi = id; bp = i; }
        }
        rv[t] = bv; ri[t] = bi; rp[t] = bp;
        __syncthreads();
        for (int s = 128; s > 0; s >>= 1) {
            if (t < s && (rv[t+s] > rv[t] || (rv[t+s] == rv[t] && ri[t+s] < ri[t]))) {
                rv[t] = rv[t+s]; ri[t] = ri[t+s]; rp[t] = rp[t+s];
            }
            __syncthreads();
        }
        if (t == 0) {
            candI[pass] = (rv[0] == -CUDART_INF_F) ? 0x7fffffff : ri[0];
            cs[rp[0]] = -CUDART_INF_F;
        }
        __syncthreads();
    }

    const float ctf1 = (float)(*ctp) + 1.0f;
    if (t < 32) {
        int idx = candI[t];
        float sc = -CUDART_INF_F;
        if (idx != 0x7fffffff) {
            const float4* mr = (const float4*)(mem + (size_t)idx * DD);
            const float4* qr = (const float4*)(g_q + q * DD);
            float dot = 0.f, mn2 = 0.f;
            #pragma unroll 8
            for (int c = 0; c < 32; c++) {
                float4 a = mr[c]; float4 b = qr[c];
                dot = fmaf(a.x, b.x, dot); dot = fmaf(a.y, b.y, dot);
                dot = fmaf(a.z, b.z, dot); dot = fmaf(a.w, b.w, dot);
                mn2 = fmaf(a.x, a.x, mn2); mn2 = fmaf(a.y, a.y, mn2);
                mn2 = fmaf(a.z, a.z, mn2); mn2 = fmaf(a.w, a.w, mn2);
            }
            float den = fmaxf(g_qn[q] * sqrtf(mn2), 1e-8f);
            float rec = ((float)ts[idx] + 1.0f) / ctf1;
            sc = (0.7f * dot / den + 0.3f * rec) * fmaf(0.5f, imp[idx], 0.5f);
        }
        exS[t] = sc; exI[t] = idx;
    }
    __syncthreads();

    if (t == 0) {
        for (int pass = 0; pass < KTOP; pass++) {
            float bv = -CUDART_INF_F; int bi = 0x7fffffff, bp = 0;
            for (int i = 0; i < 32; i++)
                if (exS[i] > bv || (exS[i] == bv && exI[i] < bi)) { bv = exS[i]; bi = exI[i]; bp = i; }
            out[q*KTOP + pass]           = bv;
            out[BQ*KTOP + q*KTOP + pass] = (float)bi;
            exS[bp] = -CUDART_INF_F;
        }
    }
}

// ---------------------------------------------------------------------------
__global__ void __launch_bounds__(256)
k_nov(float* __restrict__ out) {
    __shared__ float rv[256];
    int q = blockIdx.x, t = threadIdx.x;
    float m = CUDART_INF_F;
    for (int c = t; c < NCTA; c += 256) m = fminf(m, g_minred[c*BQ + q]);
    rv[t] = m;
    __syncthreads();
    for (int s = 128; s > 0; s >>= 1) {
        if (t < s) rv[t] = fminf(rv[t], rv[t+s]);
        __syncthreads();
    }
    if (t == 0) {
        float qn = g_qn[q];
        float dist = sqrtf(fmaxf(qn*qn + rv[0], 0.0f));
        out[2*BQ*KTOP + q] = fminf(1.0f, dist * 0.1f);
    }
}

// ---------------------------------------------------------------------------
extern "C" void kernel_launch(void* const* d_in, const int* in_sizes, int n_in,
                              void* d_out, int out_size) {
    const float* query = (const float*)d_in[0];
    const float* mem   = (const float*)d_in[1];
    const float* imp   = (const float*)d_in[2];
    const int*   ts    = (const int*)d_in[3];
    const float* Wq    = (const float*)d_in[4];
    const float* bqv   = (const float*)d_in[5];
    const int*   ct    = (const int*)d_in[6];

    int N = in_sizes[1] / DD;
    float* out = (float*)d_out;

    cudaFuncSetAttribute(k_main, cudaFuncAttributeMaxDynamicSharedMemorySize, SMEM_BYTES);

    int tiles = (N + TILE_R - 1) / TILE_R;
    int tpc = (tiles + NCTA - 1) / NCTA;
    k_main<<<NCTA, TPB, SMEM_BYTES>>>(query, mem, imp, ts, Wq, bqv, ct, N, tpc);
    k_topk<<<BQ, 256>>>(mem, imp, ts, ct, out);
    k_nov<<<BQ, 256>>>(out);
}

// round 13
// speedup vs baseline: 1.7671x; 1.7671x over previous
#include <cuda_runtime.h>
#include <cuda_bf16.h>
#include <math_constants.h>
#include <cstdint>

#define DD 128
#define BQ 32
#define KTOP 16
#define TILE_R 64
#define TPB 256
#define NCTA 296
#define SCST 34

// smem byte offsets (per CTA, ~102.4 KB -> 2 CTAs/SM)
#define SM_F0   0              // fp32 tile buf 0 (32 KB)
#define SM_F1   32768          // fp32 tile buf 1 (32 KB)
#define SM_AHI  65536          // 64 rows x 256B bf16 (16 KB)
#define SM_QHI  81920          // 32 rows x 256B bf16 (8 KB)
#define SM_SC   90112          // 64*34*4 = 8704
#define SM_MN   98816          // 256 floats (quarter norms)
#define SM_RW   99840          // 64 floats
#define SM_W    100096         // 64 floats
#define SM_CB   100352         // 32 floats
#define SM_TH   100480         // 32 floats
#define SM_FLG  100608         // 32 ints
#define SM_HV   100736         // 32*16 floats (heaps)
#define SM_HX   102784         // 32*16 ints
#define SMEM_BYTES 104832

__device__ float g_q[BQ*DD];
__device__ float g_qn[BQ];
__device__ float g_cand_s[NCTA*BQ*KTOP];
__device__ int   g_cand_i[NCTA*BQ*KTOP];
__device__ float g_minred[NCTA*BQ];

// ---------------- helpers ----------------
__device__ __forceinline__ uint32_t smem_u32(const void* p) {
    uint32_t a;
    asm("{ .reg .u64 t; cvta.to.shared.u64 t, %1; cvt.u32.u64 %0, t; }" : "=r"(a) : "l"(p));
    return a;
}
__device__ __forceinline__ void cp_async16(uint32_t saddr, const void* gaddr) {
    asm volatile("cp.async.ca.shared.global [%0], [%1], 16;" :: "r"(saddr), "l"(gaddr));
}
__device__ __forceinline__ void fma2(unsigned long long& d, unsigned long long a, unsigned long long b) {
    asm("fma.rn.f32x2 %0, %1, %2, %0;" : "+l"(d) : "l"(a), "l"(b));
}
__device__ __forceinline__ void unpack2(unsigned long long v, float& lo, float& hi) {
    asm("mov.b64 {%0, %1}, %2;" : "=f"(lo), "=f"(hi) : "l"(v));
}
__device__ __forceinline__ uint32_t pack_bf16x2(float hi_elem, float lo_elem) {
    uint32_t r;
    asm("cvt.rn.bf16x2.f32 %0, %1, %2;" : "=r"(r) : "f"(hi_elem), "f"(lo_elem));
    return r;
}
__device__ __forceinline__ float rsqrt_nr(float x) {
    float r;
    asm("rsqrt.approx.f32 %0, %1;" : "=f"(r) : "f"(x));
    r = r * fmaf(-0.5f * x * r, r, 1.5f);
    return r;
}
__device__ __forceinline__ void ldsm_x4(uint32_t& r0, uint32_t& r1, uint32_t& r2, uint32_t& r3, uint32_t a) {
    asm volatile("ldmatrix.sync.aligned.m8n8.x4.shared.b16 {%0,%1,%2,%3}, [%4];"
                 : "=r"(r0), "=r"(r1), "=r"(r2), "=r"(r3) : "r"(a));
}
__device__ __forceinline__ void ldsm_x2(uint32_t& r0, uint32_t& r1, uint32_t a) {
    asm volatile("ldmatrix.sync.aligned.m8n8.x2.shared.b16 {%0,%1}, [%2];"
                 : "=r"(r0), "=r"(r1) : "r"(a));
}
__device__ __forceinline__ void mma16816(float* c, uint32_t a0, uint32_t a1, uint32_t a2, uint32_t a3,
                                         uint32_t b0, uint32_t b1) {
    asm volatile("mma.sync.aligned.m16n8k16.row.col.f32.bf16.bf16.f32 "
                 "{%0,%1,%2,%3}, {%4,%5,%6,%7}, {%8,%9}, {%0,%1,%2,%3};"
                 : "+f"(c[0]), "+f"(c[1]), "+f"(c[2]), "+f"(c[3])
                 : "r"(a0), "r"(a1), "r"(a2), "r"(a3), "r"(b0), "r"(b1));
}

// ---------------------------------------------------------------------------
// k_main: setup + bf16 HMMA dots (64-row tiles, 2 CTAs/SM) + top-16 + min-d2
// ---------------------------------------------------------------------------
__global__ void __launch_bounds__(TPB, 2)
k_main(const float* __restrict__ query, const float* __restrict__ mem,
       const float* __restrict__ imp, const int* __restrict__ ts,
       const float* __restrict__ Wq, const float* __restrict__ bqv,
       const int* __restrict__ ctp, int N, int tpc) {
    extern __shared__ char smem[];
    const uint32_t sb = smem_u32(smem);
    float* sSC  = (float*)(smem + SM_SC);
    float* sMN  = (float*)(smem + SM_MN);
    float* sRW  = (float*)(smem + SM_RW);
    float* sW   = (float*)(smem + SM_W);
    float* sCB  = (float*)(smem + SM_CB);
    float* sTH  = (float*)(smem + SM_TH);
    int*   sFLG = (int*)(smem + SM_FLG);
    float* sHV  = (float*)(smem + SM_HV);
    int*   sHX  = (int*)(smem + SM_HX);

    const int t    = threadIdx.x;
    const int wid  = t >> 5;
    const int lane = t & 31;
    const int cta  = blockIdx.x;

    // ===== setup: exact q = query @ Wq^T + bq; Qhi bf16 operand =====
    {
        float* sQT = (float*)(smem + SM_F0);
        float* sQF = (float*)(smem + SM_F1);
        for (int o = t; o < BQ*DD; o += TPB) sQT[o] = query[o];
        __syncthreads();
        for (int o = t; o < BQ*DD; o += TPB) {
            int b = o >> 7, j = o & 127;
            const float4* wr = (const float4*)(Wq + (size_t)j * DD);
            const float4* qr = (const float4*)(sQT + b * DD);
            float a0 = 0.f, a1 = 0.f, a2 = 0.f, a3 = 0.f;
            #pragma unroll 8
            for (int dd = 0; dd < 32; dd++) {
                float4 wv = wr[dd]; float4 qv = qr[dd];
                a0 = fmaf(qv.x, wv.x, a0); a1 = fmaf(qv.y, wv.y, a1);
                a2 = fmaf(qv.z, wv.z, a2); a3 = fmaf(qv.w, wv.w, a3);
            }
            float v = ((a0 + a1) + (a2 + a3)) + bqv[j];
            sQF[o] = v;
            g_q[o] = v;
        }
        __syncthreads();
        if (t < BQ) {
            float s = 0.f;
            for (int jj = 0; jj < DD; jj++) {
                int j = (jj + 5*t) & 127;
                float v = sQF[t*DD + j];
                s = fmaf(v, v, s);
            }
            float qn = sqrtf(s);
            g_qn[t] = qn;
            sCB[t] = 0.7f / qn;
            sTH[t] = -CUDART_INF_F;
            sFLG[t] = 0;
        }
        for (int o = t; o < BQ*KTOP; o += TPB) { sHV[o] = -CUDART_INF_F; sHX[o] = 0x7fffffff; }
        for (int o = t; o < BQ*DD; o += TPB) {
            int b = o >> 7, j = o & 127;
            *(__nv_bfloat16*)(smem + SM_QHI + b*256 + (((j >> 3) ^ (b & 7)) << 4) + (j & 7)*2)
                = __float2bfloat16(sQF[o]);
        }
        __syncthreads();
    }

    const float inv_ct1 = 1.0f / ((float)(*ctp) + 1.0f);

    float lmn[4];
    #pragma unroll
    for (int j = 0; j < 4; j++) lmn[j] = CUDART_INF_F;

    const long tile0 = (long)cta * tpc;

    // convert assignment: row cr = t&63, quarter qh = t>>6 (8 chunks each)
    const int cr = t & 63;
    const int qh = t >> 6;
    // mma assignment: 8 warps = 4 row-slabs x 2 query-halves
    const int rsl = (wid & 3) * 16;
    const int qhf = wid >> 2;
    const int rA  = rsl + (lane & 15);
    const uint32_t aBase = sb + SM_AHI + rA * 256;
    const int aSel = lane >> 4;
    const int qB   = lane & 7;
    const int bSel = (lane >> 3) & 1;
    const int gid  = lane >> 2;
    const int tig  = lane & 3;

    // prologue: stage tile 0 into F0
    {
        int base = (int)(tile0 * TILE_R);
        if (base < N) {
            const float4* gsrc = (const float4*)mem + (size_t)base * (DD/4);
            if (base + TILE_R <= N) {
                #pragma unroll
                for (int j = 0; j < 8; j++) {
                    int fi = t + TPB*j, row = fi >> 5, c = fi & 31;
                    cp_async16(sb + SM_F0 + (uint32_t)(row*DD + ((c ^ (row & 31)) << 2))*4u, gsrc + fi);
                }
                asm volatile("cp.async.commit_group;");
            } else {
                float* raw = (float*)(smem + SM_F0);
                for (int j = 0; j < 8; j++) {
                    int fi = t + TPB*j, row = fi >> 5, c = fi & 31;
                    float4 v = make_float4(0.f, 0.f, 0.f, 0.f);
                    if (base + row < N) v = gsrc[fi];
                    *(float4*)(raw + row*DD + ((c ^ (row & 31)) << 2)) = v;
                }
            }
        }
    }

    for (int it = 0; it < tpc; it++) {
        int base = (int)((tile0 + it) * TILE_R);
        if (base >= N) break;
        const int curF = (it & 1) ? SM_F1 : SM_F0;

        asm volatile("cp.async.wait_group 0;" ::: "memory");
        __syncthreads();     // data landed; also orders prior phase B

        // stage next tile into other buffer (overlaps convert+mma+scan)
        {
            int nbase = (int)((tile0 + it + 1) * TILE_R);
            if (it + 1 < tpc && nbase < N) {
                const int nF = ((it + 1) & 1) ? SM_F1 : SM_F0;
                const float4* gsrc = (const float4*)mem + (size_t)nbase * (DD/4);
                if (nbase + TILE_R <= N) {
                    #pragma unroll
                    for (int j = 0; j < 8; j++) {
                        int fi = t + TPB*j, row = fi >> 5, c = fi & 31;
                        cp_async16(sb + nF + (uint32_t)(row*DD + ((c ^ (row & 31)) << 2))*4u, gsrc + fi);
                    }
                    asm volatile("cp.async.commit_group;");
                } else {
                    float* raw = (float*)(smem + nF);
                    for (int j = 0; j < 8; j++) {
                        int fi = t + TPB*j, row = fi >> 5, c = fi & 31;
                        float4 v = make_float4(0.f, 0.f, 0.f, 0.f);
                        if (nbase + row < N) v = gsrc[fi];
                        *(float4*)(raw + row*DD + ((c ^ (row & 31)) << 2)) = v;
                    }
                }
            }
        }

        // per-row scalars
        if (t < TILE_R) {
            int row = base + t;
            if (row < N) {
                sRW[t] = 0.3f * ((float)ts[row] + 1.0f) * inv_ct1;
                sW[t]  = fmaf(0.5f, imp[row], 0.5f);
            }
        }

        // convert fp32 -> Ahi bf16 (ldmatrix swizzle) + quarter norms
        {
            const float* ra = (const float*)(smem + curF) + cr*DD;
            unsigned long long nacc = 0ULL;
            #pragma unroll
            for (int cc = 0; cc < 8; cc++) {
                int lc = qh*8 + cc;                        // logical chunk
                float4 v = *(const float4*)(ra + ((lc ^ (cr & 31)) << 2));
                ulonglong2 u = *reinterpret_cast<ulonglong2*>(&v);
                fma2(nacc, u.x, u.x);
                fma2(nacc, u.y, u.y);
                uint2 w2;
                w2.x = pack_bf16x2(v.y, v.x);
                w2.y = pack_bf16x2(v.w, v.z);
                int c16 = lc >> 1, half = lc & 1;
                *(uint2*)(smem + SM_AHI + cr*256 + ((c16 ^ (cr & 7)) << 4) + half*8) = w2;
            }
            float nlo, nhi; unpack2(nacc, nlo, nhi);
            sMN[qh*TILE_R + cr] = nlo + nhi;
        }
        __syncthreads();

        // ---- HMMA: 16-row slab x 16-query half, K=128 ----
        float C[2][4];
        #pragma unroll
        for (int nt = 0; nt < 2; nt++)
            #pragma unroll
            for (int i = 0; i < 4; i++) C[nt][i] = 0.f;

        const uint32_t qb0 = sb + SM_QHI + (qhf*16 + 0*8 + qB)*256;
        const uint32_t qb1 = sb + SM_QHI + (qhf*16 + 1*8 + qB)*256;
        #pragma unroll
        for (int ks = 0; ks < 8; ks++) {
            uint32_t a0, a1, a2, a3;
            ldsm_x4(a0, a1, a2, a3, aBase + (((2*ks + aSel) ^ (rA & 7)) << 4));
            uint32_t swz = ((2*ks + bSel) ^ qB) << 4;
            uint32_t b0, b1;
            ldsm_x2(b0, b1, qb0 + swz); mma16816(C[0], a0, a1, a2, a3, b0, b1);
            ldsm_x2(b0, b1, qb1 + swz); mma16816(C[1], a0, a1, a2, a3, b0, b1);
        }

        // ---- epilogue: scores + min-d2 ----
        {
            int rla = rsl + gid, rlb = rla + 8;
            bool va = (base + rla < N), vb = (base + rlb < N);
            float mnA = sMN[rla] + sMN[64+rla] + sMN[128+rla] + sMN[192+rla];
            float mnB = sMN[rlb] + sMN[64+rlb] + sMN[128+rlb] + sMN[192+rlb];
            float invA = va ? rsqrt_nr(mnA) : 0.f;
            float invB = vb ? rsqrt_nr(mnB) : 0.f;
            float recA = va ? sRW[rla] : 0.f, wA = va ? sW[rla] : 0.f;
            float recB = vb ? sRW[rlb] : 0.f, wB = vb ? sW[rlb] : 0.f;
            #pragma unroll
            for (int nt = 0; nt < 2; nt++) {
                int q0 = qhf*16 + nt*8 + tig*2;
                float cb0 = sCB[q0], cb1 = sCB[q0+1];
                float dA0 = C[nt][0], dA1 = C[nt][1];
                float dB0 = C[nt][2], dB1 = C[nt][3];
                float2 sa, sbv;
                sa.x  = va ? fmaf(dA0*invA, cb0, recA) * wA : -CUDART_INF_F;
                sa.y  = va ? fmaf(dA1*invA, cb1, recA) * wA : -CUDART_INF_F;
                sbv.x = vb ? fmaf(dB0*invB, cb0, recB) * wB : -CUDART_INF_F;
                sbv.y = vb ? fmaf(dB1*invB, cb1, recB) * wB : -CUDART_INF_F;
                *(float2*)(sSC + rla*SCST + q0) = sa;
                *(float2*)(sSC + rlb*SCST + q0) = sbv;
                float m0 = CUDART_INF_F, m1 = CUDART_INF_F;
                if (va) { m0 = fmaf(-2.f, dA0, mnA); m1 = fmaf(-2.f, dA1, mnA); }
                if (vb) { m0 = fminf(m0, fmaf(-2.f, dB0, mnB)); m1 = fminf(m1, fmaf(-2.f, dB1, mnB)); }
                lmn[nt*2]   = fminf(lmn[nt*2],   m0);
                lmn[nt*2+1] = fminf(lmn[nt*2+1], m1);
            }
        }
        __syncthreads();

        // ---- phase A: parallel reject test (256 thr: 8-row chunks x 32 q) ----
        {
            int q = t & 31, chk = t >> 5;
            const float* col = sSC + (chk*8)*SCST + q;
            float mx = -CUDART_INF_F;
            #pragma unroll
            for (int j = 0; j < 8; j++) mx = fmaxf(mx, col[j*SCST]);
            if (mx > sTH[q]) sFLG[q] = 1;
        }
        __syncthreads();

        // ---- phase B: full 64-row scan only when flagged (rare) ----
        if (t < BQ && sFLG[t]) {
            sFLG[t] = 0;
            float th = sTH[t];
            float* hv = sHV + t*KTOP;
            int*   hx = sHX + t*KTOP;
            for (int e = 0; e < TILE_R; e += 4) {
                float v0 = sSC[(e+0)*SCST + t];
                float v1 = sSC[(e+1)*SCST + t];
                float v2 = sSC[(e+2)*SCST + t];
                float v3 = sSC[(e+3)*SCST + t];
                float mx = fmaxf(fmaxf(v0, v1), fmaxf(v2, v3));
                if (mx > th) {
                    #pragma unroll
                    for (int u = 0; u < 4; u++) {
                        float sc = (u==0)?v0:(u==1)?v1:(u==2)?v2:v3;
                        if (sc > th) {
                            int idx = base + e + u;
                            int pos = KTOP - 1;
                            #pragma unroll
                            for (int s = KTOP - 1; s > 0; s--)
                                if (sc > hv[s-1]) { hv[s] = hv[s-1]; hx[s] = hx[s-1]; pos = s-1; }
                            hv[pos] = sc; hx[pos] = idx;
                            th = hv[KTOP-1];
                        }
                    }
                }
            }
            sTH[t] = th;
        }
        // no barrier: next iter's post-wait __syncthreads orders phase B
    }
    __syncthreads();

    // ---- reduce lmn: q = qhf*16 + nt*8 + tig*2 + p; 32 contributors/q ----
    #pragma unroll
    for (int nt = 0; nt < 2; nt++)
        #pragma unroll
        for (int p = 0; p < 2; p++) {
            int q = qhf*16 + nt*8 + tig*2 + p;
            sSC[q*32 + (wid & 3)*8 + gid] = lmn[nt*2+p];
        }
    __syncthreads();
    if (t < BQ) {
        float m = CUDART_INF_F;
        #pragma unroll 4
        for (int i = 0; i < 32; i++) m = fminf(m, sSC[t*32 + ((i + t) & 31)]);
        g_minred[cta*BQ + t] = m;
        float* cs = g_cand_s + ((size_t)cta*BQ + t) * KTOP;
        int*   ci = g_cand_i + ((size_t)cta*BQ + t) * KTOP;
        #pragma unroll
        for (int j = 0; j < KTOP; j++) { cs[j] = sHV[t*KTOP + j]; ci[j] = sHX[t*KTOP + j]; }
    }
}

// ---------------------------------------------------------------------------
// k_topk: approx top-32 merge, exact fp32 rescoring, emit exact top-16
// ---------------------------------------------------------------------------
#define MCAND (NCTA*KTOP)
__global__ void __launch_bounds__(256)
k_topk(const float* __restrict__ mem, const float* __restrict__ imp,
       const int* __restrict__ ts, const int* __restrict__ ctp,
       float* __restrict__ out) {
    __shared__ float cs[MCAND];
    __shared__ int   ci[MCAND];
    __shared__ float rv[256];
    __shared__ int   ri[256], rp[256];
    __shared__ int   candI[32];
    __shared__ float exS[32];
    __shared__ int   exI[32];

    int q = blockIdx.x;
    int t = threadIdx.x;

    for (int i = t; i < MCAND; i += 256) {
        int c = i >> 4, j = i & (KTOP-1);
        size_t g = ((size_t)c*BQ + q) * KTOP + j;
        cs[i] = g_cand_s[g];
        ci[i] = g_cand_i[g];
    }
    __syncthreads();

    for (int pass = 0; pass < 32; pass++) {
        float bv = -CUDART_INF_F; int bi = 0x7fffffff, bp = 0;
        for (int i = t; i < MCAND; i += 256) {
            float v = cs[i]; int id = ci[i];
            if (v > bv || (v == bv && id < bi)) { bv = v; bi = id; bp = i; }
        }
        rv[t] = bv; ri[t] = bi; rp[t] = bp;
        __syncthreads();
        for (int s = 128; s > 0; s >>= 1) {
            if (t < s && (rv[t+s] > rv[t] || (rv[t+s] == rv[t] && ri[t+s] < ri[t]))) {
                rv[t] = rv[t+s]; ri[t] = ri[t+s]; rp[t] = rp[t+s];
            }
            __syncthreads();
        }
        if (t == 0) {
            candI[pass] = (rv[0] == -CUDART_INF_F) ? 0x7fffffff : ri[0];
            cs[rp[0]] = -CUDART_INF_F;
        }
        __syncthreads();
    }

    const float ctf1 = (float)(*ctp) + 1.0f;
    if (t < 32) {
        int idx = candI[t];
        float sc = -CUDART_INF_F;
        if (idx != 0x7fffffff) {
            const float4* mr = (const float4*)(mem + (size_t)idx * DD);
            const float4* qr = (const float4*)(g_q + q * DD);
            float dot = 0.f, mn2 = 0.f;
            #pragma unroll 8
            for (int c = 0; c < 32; c++) {
                float4 a = mr[c]; float4 b = qr[c];
                dot = fmaf(a.x, b.x, dot); dot = fmaf(a.y, b.y, dot);
                dot = fmaf(a.z, b.z, dot); dot = fmaf(a.w, b.w, dot);
                mn2 = fmaf(a.x, a.x, mn2); mn2 = fmaf(a.y, a.y, mn2);
                mn2 = fmaf(a.z, a.z, mn2); mn2 = fmaf(a.w, a.w, mn2);
            }
            float den = fmaxf(g_qn[q] * sqrtf(mn2), 1e-8f);
            float rec = ((float)ts[idx] + 1.0f) / ctf1;
            sc = (0.7f * dot / den + 0.3f * rec) * fmaf(0.5f, imp[idx], 0.5f);
        }
        exS[t] = sc; exI[t] = idx;
    }
    __syncthreads();

    if (t == 0) {
        for (int pass = 0; pass < KTOP; pass++) {
            float bv = -CUDART_INF_F; int bi = 0x7fffffff, bp = 0;
            for (int i = 0; i < 32; i++)
                if (exS[i] > bv || (exS[i] == bv && exI[i] < bi)) { bv = exS[i]; bi = exI[i]; bp = i; }
            out[q*KTOP + pass]           = bv;
            out[BQ*KTOP + q*KTOP + pass] = (float)bi;
            exS[bp] = -CUDART_INF_F;
        }
    }
}

// ---------------------------------------------------------------------------
__global__ void __launch_bounds__(256)
k_nov(float* __restrict__ out) {
    __shared__ float rv[256];
    int q = blockIdx.x, t = threadIdx.x;
    float m = CUDART_INF_F;
    for (int c = t; c < NCTA; c += 256) m = fminf(m, g_minred[c*BQ + q]);
    rv[t] = m;
    __syncthreads();
    for (int s = 128; s > 0; s >>= 1) {
        if (t < s) rv[t] = fminf(rv[t], rv[t+s]);
        __syncthreads();
    }
    if (t == 0) {
        float qn = g_qn[q];
        float dist = sqrtf(fmaxf(qn*qn + rv[0], 0.0f));
        out[2*BQ*KTOP + q] = fminf(1.0f, dist * 0.1f);
    }
}

// ---------------------------------------------------------------------------
extern "C" void kernel_launch(void* const* d_in, const int* in_sizes, int n_in,
                              void* d_out, int out_size) {
    const float* query = (const float*)d_in[0];
    const float* mem   = (const float*)d_in[1];
    const float* imp   = (const float*)d_in[2];
    const int*   ts    = (const int*)d_in[3];
    const float* Wq    = (const float*)d_in[4];
    const float* bqv   = (const float*)d_in[5];
    const int*   ct    = (const int*)d_in[6];

    int N = in_sizes[1] / DD;
    float* out = (float*)d_out;

    cudaFuncSetAttribute(k_main, cudaFuncAttributeMaxDynamicSharedMemorySize, SMEM_BYTES);

    int tiles = (N + TILE_R - 1) / TILE_R;
    int tpc = (tiles + NCTA - 1) / NCTA;
    k_main<<<NCTA, TPB, SMEM_BYTES>>>(query, mem, imp, ts, Wq, bqv, ct, N, tpc);
    k_topk<<<BQ, 256>>>(mem, imp, ts, ct, out);
    k_nov<<<BQ, 256>>>(out);
}

// round 14
// speedup vs baseline: 1.7784x; 1.0064x over previous
#include <cuda_runtime.h>
#include <cuda_bf16.h>
#include <math_constants.h>
#include <cstdint>

#define DD 128
#define BQ 32
#define KTOP 16
#define TILE_R 64
#define TPB 256
#define NCTA 296
#define SCST 34

// smem byte offsets (per CTA, ~102.4 KB -> 2 CTAs/SM)
#define SM_F0   0              // fp32 tile buf 0 (32 KB)
#define SM_F1   32768          // fp32 tile buf 1 (32 KB)
#define SM_AHI  65536          // 64 rows x 256B bf16 (16 KB)
#define SM_QHI  81920          // 32 rows x 256B bf16 (8 KB)
#define SM_SC   90112          // 64*34*4 = 8704
#define SM_MN   98816          // 256 floats (quarter norms)
#define SM_RW   99840          // 64 floats
#define SM_W    100096         // 64 floats
#define SM_CB   100352         // 32 floats
#define SM_TH   100480         // 32 floats
#define SM_FLG  100608         // 32 ints
#define SM_HV   100736         // 32*16 floats (heaps)
#define SM_HX   102784         // 32*16 ints
#define SMEM_BYTES 104832

__device__ float g_q[BQ*DD];
__device__ float g_qn[BQ];
__device__ float g_cand_s[NCTA*BQ*KTOP];
__device__ int   g_cand_i[NCTA*BQ*KTOP];
__device__ float g_minred[NCTA*BQ];

// ---------------- helpers ----------------
__device__ __forceinline__ uint32_t smem_u32(const void* p) {
    uint32_t a;
    asm("{ .reg .u64 t; cvta.to.shared.u64 t, %1; cvt.u32.u64 %0, t; }" : "=r"(a) : "l"(p));
    return a;
}
__device__ __forceinline__ void cp_async16(uint32_t saddr, const void* gaddr) {
    asm volatile("cp.async.ca.shared.global [%0], [%1], 16;" :: "r"(saddr), "l"(gaddr));
}
__device__ __forceinline__ void fma2(unsigned long long& d, unsigned long long a, unsigned long long b) {
    asm("fma.rn.f32x2 %0, %1, %2, %0;" : "+l"(d) : "l"(a), "l"(b));
}
__device__ __forceinline__ void unpack2(unsigned long long v, float& lo, float& hi) {
    asm("mov.b64 {%0, %1}, %2;" : "=f"(lo), "=f"(hi) : "l"(v));
}
__device__ __forceinline__ uint32_t pack_bf16x2(float hi_elem, float lo_elem) {
    uint32_t r;
    asm("cvt.rn.bf16x2.f32 %0, %1, %2;" : "=r"(r) : "f"(hi_elem), "f"(lo_elem));
    return r;
}
__device__ __forceinline__ float rsqrt_nr(float x) {
    float r;
    asm("rsqrt.approx.f32 %0, %1;" : "=f"(r) : "f"(x));
    r = r * fmaf(-0.5f * x * r, r, 1.5f);
    return r;
}
__device__ __forceinline__ void ldsm_x4(uint32_t& r0, uint32_t& r1, uint32_t& r2, uint32_t& r3, uint32_t a) {
    asm volatile("ldmatrix.sync.aligned.m8n8.x4.shared.b16 {%0,%1,%2,%3}, [%4];"
                 : "=r"(r0), "=r"(r1), "=r"(r2), "=r"(r3) : "r"(a));
}
__device__ __forceinline__ void ldsm_x2(uint32_t& r0, uint32_t& r1, uint32_t a) {
    asm volatile("ldmatrix.sync.aligned.m8n8.x2.shared.b16 {%0,%1}, [%2];"
                 : "=r"(r0), "=r"(r1) : "r"(a));
}
__device__ __forceinline__ void mma16816(float* c, uint32_t a0, uint32_t a1, uint32_t a2, uint32_t a3,
                                         uint32_t b0, uint32_t b1) {
    asm volatile("mma.sync.aligned.m16n8k16.row.col.f32.bf16.bf16.f32 "
                 "{%0,%1,%2,%3}, {%4,%5,%6,%7}, {%8,%9}, {%0,%1,%2,%3};"
                 : "+f"(c[0]), "+f"(c[1]), "+f"(c[2]), "+f"(c[3])
                 : "r"(a0), "r"(a1), "r"(a2), "r"(a3), "r"(b0), "r"(b1));
}

// ---------------------------------------------------------------------------
// k_main: pair-decoupled bf16 HMMA dots (64-row tiles, 2 CTAs/SM)
// ---------------------------------------------------------------------------
__global__ void __launch_bounds__(TPB, 2)
k_main(const float* __restrict__ query, const float* __restrict__ mem,
       const float* __restrict__ imp, const int* __restrict__ ts,
       const float* __restrict__ Wq, const float* __restrict__ bqv,
       const int* __restrict__ ctp, int N, int tpc) {
    extern __shared__ char smem[];
    const uint32_t sb = smem_u32(smem);
    float* sSC  = (float*)(smem + SM_SC);
    float* sMN  = (float*)(smem + SM_MN);
    float* sRW  = (float*)(smem + SM_RW);
    float* sW   = (float*)(smem + SM_W);
    float* sCB  = (float*)(smem + SM_CB);
    float* sTH  = (float*)(smem + SM_TH);
    int*   sFLG = (int*)(smem + SM_FLG);
    float* sHV  = (float*)(smem + SM_HV);
    int*   sHX  = (int*)(smem + SM_HX);

    const int t    = threadIdx.x;
    const int wid  = t >> 5;
    const int lane = t & 31;
    const int cta  = blockIdx.x;

    // ===== setup: exact q = query @ Wq^T + bq; Qhi bf16 operand =====
    {
        float* sQT = (float*)(smem + SM_F0);
        float* sQF = (float*)(smem + SM_F1);
        for (int o = t; o < BQ*DD; o += TPB) sQT[o] = query[o];
        __syncthreads();
        for (int o = t; o < BQ*DD; o += TPB) {
            int b = o >> 7, j = o & 127;
            const float4* wr = (const float4*)(Wq + (size_t)j * DD);
            const float4* qr = (const float4*)(sQT + b * DD);
            float a0 = 0.f, a1 = 0.f, a2 = 0.f, a3 = 0.f;
            #pragma unroll 8
            for (int dd = 0; dd < 32; dd++) {
                float4 wv = wr[dd]; float4 qv = qr[dd];
                a0 = fmaf(qv.x, wv.x, a0); a1 = fmaf(qv.y, wv.y, a1);
                a2 = fmaf(qv.z, wv.z, a2); a3 = fmaf(qv.w, wv.w, a3);
            }
            float v = ((a0 + a1) + (a2 + a3)) + bqv[j];
            sQF[o] = v;
            g_q[o] = v;
        }
        __syncthreads();
        if (t < BQ) {
            float s = 0.f;
            for (int jj = 0; jj < DD; jj++) {
                int j = (jj + 5*t) & 127;
                float v = sQF[t*DD + j];
                s = fmaf(v, v, s);
            }
            float qn = sqrtf(s);
            g_qn[t] = qn;
            sCB[t] = 0.7f / qn;
            sTH[t] = -CUDART_INF_F;
            sFLG[t] = 0;
        }
        for (int o = t; o < BQ*KTOP; o += TPB) { sHV[o] = -CUDART_INF_F; sHX[o] = 0x7fffffff; }
        for (int o = t; o < BQ*DD; o += TPB) {
            int b = o >> 7, j = o & 127;
            *(__nv_bfloat16*)(smem + SM_QHI + b*256 + (((j >> 3) ^ (b & 7)) << 4) + (j & 7)*2)
                = __float2bfloat16(sQF[o]);
        }
        __syncthreads();
    }

    const float inv_ct1 = 1.0f / ((float)(*ctp) + 1.0f);

    float lmn[4];
    #pragma unroll
    for (int j = 0; j < 4; j++) lmn[j] = CUDART_INF_F;

    const long tile0 = (long)cta * tpc;

    // pair/slab assignment
    const int p    = wid & 3;            // slab / pair id
    const int m    = wid >> 2;           // pair member (0/1)
    const int tp   = m*32 + lane;        // 0..63 within pair
    const int crow = p*16 + (tp & 15);   // convert row owned by this thread
    const int cqh  = tp >> 4;            // chunk quarter 0..3
    const int rsl  = p * 16;
    const int qhf  = m;                  // query half for mma
    const int rA   = rsl + (lane & 15);
    const uint32_t aBase = sb + SM_AHI + rA * 256;
    const int aSel = lane >> 4;
    const int qB   = lane & 7;
    const int bSel = (lane >> 3) & 1;
    const int gid  = lane >> 2;
    const int tig  = lane & 3;

    // prologue: stage tile 0 into F0
    {
        int base = (int)(tile0 * TILE_R);
        if (base < N) {
            const float4* gsrc = (const float4*)mem + (size_t)base * (DD/4);
            if (base + TILE_R <= N) {
                #pragma unroll
                for (int j = 0; j < 8; j++) {
                    int fi = t + TPB*j, row = fi >> 5, c = fi & 31;
                    cp_async16(sb + SM_F0 + (uint32_t)(row*DD + ((c ^ (row & 31)) << 2))*4u, gsrc + fi);
                }
                asm volatile("cp.async.commit_group;");
            } else {
                float* raw = (float*)(smem + SM_F0);
                for (int j = 0; j < 8; j++) {
                    int fi = t + TPB*j, row = fi >> 5, c = fi & 31;
                    float4 v = make_float4(0.f, 0.f, 0.f, 0.f);
                    if (base + row < N) v = gsrc[fi];
                    *(float4*)(raw + row*DD + ((c ^ (row & 31)) << 2)) = v;
                }
            }
        }
    }

    for (int it = 0; it < tpc; it++) {
        int base = (int)((tile0 + it) * TILE_R);
        if (base >= N) break;
        const int curF = (it & 1) ? SM_F1 : SM_F0;

        // ---- issue NEXT tile staging BEFORE the wait (buffer free since it-1) ----
        bool nxt_async = false;
        {
            int nbase = (int)((tile0 + it + 1) * TILE_R);
            if (it + 1 < tpc && nbase < N) {
                const int nF = ((it + 1) & 1) ? SM_F1 : SM_F0;
                const float4* gsrc = (const float4*)mem + (size_t)nbase * (DD/4);
                if (nbase + TILE_R <= N) {
                    #pragma unroll
                    for (int j = 0; j < 8; j++) {
                        int fi = t + TPB*j, row = fi >> 5, c = fi & 31;
                        cp_async16(sb + nF + (uint32_t)(row*DD + ((c ^ (row & 31)) << 2))*4u, gsrc + fi);
                    }
                    asm volatile("cp.async.commit_group;");
                    nxt_async = true;
                } else {
                    float* raw = (float*)(smem + nF);
                    for (int j = 0; j < 8; j++) {
                        int fi = t + TPB*j, row = fi >> 5, c = fi & 31;
                        float4 v = make_float4(0.f, 0.f, 0.f, 0.f);
                        if (nbase + row < N) v = gsrc[fi];
                        *(float4*)(raw + row*DD + ((c ^ (row & 31)) << 2)) = v;
                    }
                }
            }
        }
        if (nxt_async) asm volatile("cp.async.wait_group 1;" ::: "memory");
        else           asm volatile("cp.async.wait_group 0;" ::: "memory");
        __syncthreads();    // tile i visible; also orders prior phase B vs new epilogue

        // ---- pair-local per-row scalars (rows of own slab) ----
        if (tp < 16) {
            int r = p*16 + tp;
            int row = base + r;
            if (row < N) {
                sRW[r] = 0.3f * ((float)ts[row] + 1.0f) * inv_ct1;
                sW[r]  = fmaf(0.5f, imp[row], 0.5f);
            }
        }

        // ---- pair-local convert: own slab rows -> AHI bf16 + quarter norms ----
        {
            const float* ra = (const float*)(smem + curF) + crow*DD;
            unsigned long long nacc = 0ULL;
            #pragma unroll
            for (int cc = 0; cc < 8; cc++) {
                int lc = cqh*8 + cc;
                float4 v = *(const float4*)(ra + ((lc ^ (crow & 31)) << 2));
                ulonglong2 u = *reinterpret_cast<ulonglong2*>(&v);
                fma2(nacc, u.x, u.x);
                fma2(nacc, u.y, u.y);
                uint2 w2;
                w2.x = pack_bf16x2(v.y, v.x);
                w2.y = pack_bf16x2(v.w, v.z);
                int c16 = lc >> 1, half = lc & 1;
                *(uint2*)(smem + SM_AHI + crow*256 + ((c16 ^ (crow & 7)) << 4) + half*8) = w2;
            }
            float nlo, nhi; unpack2(nacc, nlo, nhi);
            sMN[cqh*TILE_R + crow] = nlo + nhi;
        }
        // pair barrier: this slab's AHI/norms/scalars ready for this pair's MMA
        asm volatile("bar.sync %0, %1;" :: "r"(p + 1), "r"(64) : "memory");

        // ---- HMMA: 16-row slab x 16-query half, K=128 ----
        float C[2][4];
        #pragma unroll
        for (int nt = 0; nt < 2; nt++)
            #pragma unroll
            for (int i = 0; i < 4; i++) C[nt][i] = 0.f;

        const uint32_t qb0 = sb + SM_QHI + (qhf*16 + 0*8 + qB)*256;
        const uint32_t qb1 = sb + SM_QHI + (qhf*16 + 1*8 + qB)*256;
        #pragma unroll
        for (int ks = 0; ks < 8; ks++) {
            uint32_t a0, a1, a2, a3;
            ldsm_x4(a0, a1, a2, a3, aBase + (((2*ks + aSel) ^ (rA & 7)) << 4));
            uint32_t swz = ((2*ks + bSel) ^ qB) << 4;
            uint32_t b0, b1;
            ldsm_x2(b0, b1, qb0 + swz); mma16816(C[0], a0, a1, a2, a3, b0, b1);
            ldsm_x2(b0, b1, qb1 + swz); mma16816(C[1], a0, a1, a2, a3, b0, b1);
        }

        // ---- epilogue: scores + min-d2 + in-register flag reduction ----
        {
            int rla = rsl + gid, rlb = rla + 8;
            bool va = (base + rla < N), vb = (base + rlb < N);
            float mnA = sMN[rla] + sMN[64+rla] + sMN[128+rla] + sMN[192+rla];
            float mnB = sMN[rlb] + sMN[64+rlb] + sMN[128+rlb] + sMN[192+rlb];
            float invA = va ? rsqrt_nr(mnA) : 0.f;
            float invB = vb ? rsqrt_nr(mnB) : 0.f;
            float recA = va ? sRW[rla] : 0.f, wA = va ? sW[rla] : 0.f;
            float recB = vb ? sRW[rlb] : 0.f, wB = vb ? sW[rlb] : 0.f;
            #pragma unroll
            for (int nt = 0; nt < 2; nt++) {
                int q0 = qhf*16 + nt*8 + tig*2;
                float cb0 = sCB[q0], cb1 = sCB[q0+1];
                float dA0 = C[nt][0], dA1 = C[nt][1];
                float dB0 = C[nt][2], dB1 = C[nt][3];
                float2 sa, sbv;
                sa.x  = va ? fmaf(dA0*invA, cb0, recA) * wA : -CUDART_INF_F;
                sa.y  = va ? fmaf(dA1*invA, cb1, recA) * wA : -CUDART_INF_F;
                sbv.x = vb ? fmaf(dB0*invB, cb0, recB) * wB : -CUDART_INF_F;
                sbv.y = vb ? fmaf(dB1*invB, cb1, recB) * wB : -CUDART_INF_F;
                *(float2*)(sSC + rla*SCST + q0) = sa;
                *(float2*)(sSC + rlb*SCST + q0) = sbv;
                float m0 = CUDART_INF_F, m1 = CUDART_INF_F;
                if (va) { m0 = fmaf(-2.f, dA0, mnA); m1 = fmaf(-2.f, dA1, mnA); }
                if (vb) { m0 = fminf(m0, fmaf(-2.f, dB0, mnB)); m1 = fminf(m1, fmaf(-2.f, dB1, mnB)); }
                lmn[nt*2]   = fminf(lmn[nt*2],   m0);
                lmn[nt*2+1] = fminf(lmn[nt*2+1], m1);
                // in-register per-warp max over this slab's 16 rows for q0/q0+1
                float mq0 = fmaxf(sa.x, sbv.x);
                float mq1 = fmaxf(sa.y, sbv.y);
                #pragma unroll
                for (int off = 4; off < 32; off <<= 1) {
                    mq0 = fmaxf(mq0, __shfl_xor_sync(0xffffffffu, mq0, off));
                    mq1 = fmaxf(mq1, __shfl_xor_sync(0xffffffffu, mq1, off));
                }
                if (gid == 0) {
                    if (mq0 > sTH[q0])   sFLG[q0]   = 1;
                    if (mq1 > sTH[q0+1]) sFLG[q0+1] = 1;
                }
            }
        }
        __syncthreads();

        // ---- phase B: full 64-row scan only when flagged ----
        if (t < BQ && sFLG[t]) {
            sFLG[t] = 0;
            float th = sTH[t];
            float* hv = sHV + t*KTOP;
            int*   hx = sHX + t*KTOP;
            for (int e = 0; e < TILE_R; e += 4) {
                float v0 = sSC[(e+0)*SCST + t];
                float v1 = sSC[(e+1)*SCST + t];
                float v2 = sSC[(e+2)*SCST + t];
                float v3 = sSC[(e+3)*SCST + t];
                float mx = fmaxf(fmaxf(v0, v1), fmaxf(v2, v3));
                if (mx > th) {
                    #pragma unroll
                    for (int u = 0; u < 4; u++) {
                        float sc = (u==0)?v0:(u==1)?v1:(u==2)?v2:v3;
                        if (sc > th) {
                            int idx = base + e + u;
                            int pos = KTOP - 1;
                            #pragma unroll
                            for (int s = KTOP - 1; s > 0; s--)
                                if (sc > hv[s-1]) { hv[s] = hv[s-1]; hx[s] = hx[s-1]; pos = s-1; }
                            hv[pos] = sc; hx[pos] = idx;
                            th = hv[KTOP-1];
                        }
                    }
                }
            }
            sTH[t] = th;
        }
        // no barrier: next iter's post-wait __syncthreads orders phase B
    }
    __syncthreads();

    // ---- reduce lmn: q = qhf*16 + nt*8 + tig*2 + pp; 32 contributors/q ----
    #pragma unroll
    for (int nt = 0; nt < 2; nt++)
        #pragma unroll
        for (int pp = 0; pp < 2; pp++) {
            int q = qhf*16 + nt*8 + tig*2 + pp;
            sSC[q*32 + p*8 + gid] = lmn[nt*2+pp];
        }
    __syncthreads();
    if (t < BQ) {
        float mn = CUDART_INF_F;
        #pragma unroll 4
        for (int i = 0; i < 32; i++) mn = fminf(mn, sSC[t*32 + ((i + t) & 31)]);
        g_minred[cta*BQ + t] = mn;
        float* cs = g_cand_s + ((size_t)cta*BQ + t) * KTOP;
        int*   ci = g_cand_i + ((size_t)cta*BQ + t) * KTOP;
        #pragma unroll
        for (int j = 0; j < KTOP; j++) { cs[j] = sHV[t*KTOP + j]; ci[j] = sHX[t*KTOP + j]; }
    }
}

// ---------------------------------------------------------------------------
// k_topk: approx top-32 merge, exact fp32 rescoring, emit exact top-16
// ---------------------------------------------------------------------------
#define MCAND (NCTA*KTOP)
__global__ void __launch_bounds__(256)
k_topk(const float* __restrict__ mem, const float* __restrict__ imp,
       const int* __restrict__ ts, const int* __restrict__ ctp,
       float* __restrict__ out) {
    __shared__ float cs[MCAND];
    __shared__ int   ci[MCAND];
    __shared__ float rv[256];
    __shared__ int   ri[256], rp[256];
    __shared__ int   candI[32];
    __shared__ float exS[32];
    __shared__ int   exI[32];

    int q = blockIdx.x;
    int t = threadIdx.x;

    for (int i = t; i < MCAND; i += 256) {
        int c = i >> 4, j = i & (KTOP-1);
        size_t g = ((size_t)c*BQ + q) * KTOP + j;
        cs[i] = g_cand_s[g];
        ci[i] = g_cand_i[g];
    }
    __syncthreads();

    for (int pass = 0; pass < 32; pass++) {
        float bv = -CUDART_INF_F; int bi = 0x7fffffff, bp = 0;
        for (int i = t; i < MCAND; i += 256) {
            float v = cs[i]; int id = ci[i];
            if (v > bv || (v == bv && id < bi)) { bv = v; bi = id; bp = i; }
        }
        rv[t] = bv; ri[t] = bi; rp[t] = bp;
        __syncthreads();
        for (int s = 128; s > 0; s >>= 1) {
            if (t < s && (rv[t+s] > rv[t] || (rv[t+s] == rv[t] && ri[t+s] < ri[t]))) {
                rv[t] = rv[t+s]; ri[t] = ri[t+s]; rp[t] = rp[t+s];
            }
            __syncthreads();
        }
        if (t == 0) {
            candI[pass] = (rv[0] == -CUDART_INF_F) ? 0x7fffffff : ri[0];
            cs[rp[0]] = -CUDART_INF_F;
        }
        __syncthreads();
    }

    const float ctf1 = (float)(*ctp) + 1.0f;
    if (t < 32) {
        int idx = candI[t];
        float sc = -CUDART_INF_F;
        if (idx != 0x7fffffff) {
            const float4* mr = (const float4*)(mem + (size_t)idx * DD);
            const float4* qr = (const float4*)(g_q + q * DD);
            float dot = 0.f, mn2 = 0.f;
            #pragma unroll 8
            for (int c = 0; c < 32; c++) {
                float4 a = mr[c]; float4 b = qr[c];
                dot = fmaf(a.x, b.x, dot); dot = fmaf(a.y, b.y, dot);
                dot = fmaf(a.z, b.z, dot); dot = fmaf(a.w, b.w, dot);
                mn2 = fmaf(a.x, a.x, mn2); mn2 = fmaf(a.y, a.y, mn2);
                mn2 = fmaf(a.z, a.z, mn2); mn2 = fmaf(a.w, a.w, mn2);
            }
            float den = fmaxf(g_qn[q] * sqrtf(mn2), 1e-8f);
            float rec = ((float)ts[idx] + 1.0f) / ctf1;
            sc = (0.7f * dot / den + 0.3f * rec) * fmaf(0.5f, imp[idx], 0.5f);
        }
        exS[t] = sc; exI[t] = idx;
    }
    __syncthreads();

    if (t == 0) {
        for (int pass = 0; pass < KTOP; pass++) {
            float bv = -CUDART_INF_F; int bi = 0x7fffffff, bp = 0;
            for (int i = 0; i < 32; i++)
                if (exS[i] > bv || (exS[i] == bv && exI[i] < bi)) { bv = exS[i]; bi = exI[i]; bp = i; }
            out[q*KTOP + pass]           = bv;
            out[BQ*KTOP + q*KTOP + pass] = (float)bi;
            exS[bp] = -CUDART_INF_F;
        }
    }
}

// ---------------------------------------------------------------------------
__global__ void __launch_bounds__(256)
k_nov(float* __restrict__ out) {
    __shared__ float rv[256];
    int q = blockIdx.x, t = threadIdx.x;
    float m = CUDART_INF_F;
    for (int c = t; c < NCTA; c += 256) m = fminf(m, g_minred[c*BQ + q]);
    rv[t] = m;
    __syncthreads();
    for (int s = 128; s > 0; s >>= 1) {
        if (t < s) rv[t] = fminf(rv[t], rv[t+s]);
        __syncthreads();
    }
    if (t == 0) {
        float qn = g_qn[q];
        float dist = sqrtf(fmaxf(qn*qn + rv[0], 0.0f));
        out[2*BQ*KTOP + q] = fminf(1.0f, dist * 0.1f);
    }
}

// ---------------------------------------------------------------------------
extern "C" void kernel_launch(void* const* d_in, const int* in_sizes, int n_in,
                              void* d_out, int out_size) {
    const float* query = (const float*)d_in[0];
    const float* mem   = (const float*)d_in[1];
    const float* imp   = (const float*)d_in[2];
    const int*   ts    = (const int*)d_in[3];
    const float* Wq    = (const float*)d_in[4];
    const float* bqv   = (const float*)d_in[5];
    const int*   ct    = (const int*)d_in[6];

    int N = in_sizes[1] / DD;
    float* out = (float*)d_out;

    cudaFuncSetAttribute(k_main, cudaFuncAttributeMaxDynamicSharedMemorySize, SMEM_BYTES);

    int tiles = (N + TILE_R - 1) / TILE_R;
    int tpc = (tiles + NCTA - 1) / NCTA;
    k_main<<<NCTA, TPB, SMEM_BYTES>>>(query, mem, imp, ts, Wq, bqv, ct, N, tpc);
    k_topk<<<BQ, 256>>>(mem, imp, ts, ct, out);
    k_nov<<<BQ, 256>>>(out);
}